// round 16
// baseline (speedup 1.0000x reference)
#include <cuda_runtime.h>

// Problem constants
#define BB   256
#define LL   2048
#define DD   128
#define VV   6000
#define TMAX 48

#define NTHREADS 512
#define NWARPS   16
#define SORT_CAP (LL + TMAX * 8)   // bins padded to x8 (max 7 pad each)

// Single monolithic kernel: one CTA per batch row.
//   Phase 0: atomic-free counting sort; per-token sorted index computed during
//            the histogram pass (leader RMW + shfl), scatter = 2 LDS + 1 STS.
//   wtab   : smem exp(embW) built during the 48-thread bookkeeping stage.
//   Phase 1: rank-balanced warp-per-bin FFMA accumulation, 8-deep LDG pipe.
__global__ void __launch_bounds__(NTHREADS, 2)
embedder_kernel(const float* __restrict__ X,
                const float* __restrict__ embX,
                const float* __restrict__ embW,
                float* __restrict__ out) {
    const int b    = blockIdx.x;
    const int tid  = threadIdx.x;
    const int warp = tid >> 5;
    const int lane = tid & 31;
    const int wrow = warp * TMAX;

    __shared__ float s_wtab[VV + 4];                    // exp(embW[v]), 24KB
    __shared__ __align__(16) int s_sorted[SORT_CAP];    // bin-sorted ids
    __shared__ int s_meta[LL];          // id:13 | bin:6 | idx-in-(warp,bin):7
    __shared__ int s_whist[NWARPS * TMAX];  // counts, then in-place cursors
    __shared__ int s_hist[TMAX];
    __shared__ int s_offP[TMAX + 1];
    __shared__ int s_assign[TMAX];          // (warp,slot) -> bin

    // ---------- init: zero per-warp histograms only ----------
    #pragma unroll 1
    for (int i = tid; i < NWARPS * TMAX; i += NTHREADS) s_whist[i] = 0;
    __syncthreads();

    // ---------- Phase 0a: meta + histogram + per-token sorted index ----------
    const float2* __restrict__ Xb =
        reinterpret_cast<const float2*>(X) + (size_t)b * LL;
    #pragma unroll
    for (int it = 0; it < LL / NTHREADS; ++it) {        // 4 iters, warp-uniform
        int t = it * NTHREADS + tid;
        float2 m = Xb[t];                    // m.x = T (>=0), m.y = id
        int bin = (int)m.x;                  // trunc == floor for T >= 0
        bin = min(max(bin, 0), TMAX - 1);
        int id = (int)m.y;                   // 1..5999 exact in fp32
        unsigned g = __match_any_sync(0xffffffffu, bin);
        int leader = __ffs(g) - 1;
        int rank = __popc(g & ((1u << lane) - 1u));
        int old = 0;
        if (lane == leader) {                // leader: plain RMW, race-free
            old = s_whist[wrow + bin];
            s_whist[wrow + bin] = old + __popc(g);
        }
        old = __shfl_sync(0xffffffffu, old, leader);
        // idx within (warp,bin) <= 127 -> fits 7 bits
        s_meta[t] = id | (bin << 13) | ((old + rank) << 19);
    }
    __syncthreads();

    // ---------- wtab build (all threads) overlapped with 0b (48 threads) ----
    #pragma unroll 1
    for (int i = tid; i < VV + 1; i += NTHREADS)
        s_wtab[i] = __expf(embW[i]);

    if (tid < TMAX) {
        int c = 0;
        #pragma unroll
        for (int w = 0; w < NWARPS; w++) c += s_whist[w * TMAX + tid];
        s_hist[tid] = c;
    }
    __syncthreads();

    // Rank bins by count + snake-partition into 16 warps x 3 slots.
    if (tid < TMAX) {
        int c = s_hist[tid];
        int r = 0;
        #pragma unroll 8
        for (int j = 0; j < TMAX; j++) {
            int cj = s_hist[j];
            r += (cj > c) || (cj == c && j < tid);
        }
        int w, slot;
        if (r < NWARPS)          { w = r;                  slot = 0; }
        else if (r < 2 * NWARPS) { w = 2 * NWARPS - 1 - r; slot = 1; }
        else                     { w = r - 2 * NWARPS;     slot = 2; }
        s_assign[w * 3 + slot] = tid;
    }
    // Padded (x8) exclusive prefix (pad ids = 0 == zero embX row).
    if (tid == 0) {
        int acc = 0;
        #pragma unroll
        for (int i = 0; i < TMAX; i++) {
            s_offP[i] = acc;
            acc += (s_hist[i] + 7) & ~7;
        }
        s_offP[TMAX] = acc;
    }
    __syncthreads();

    // In-place cursor bases + zero ONLY the pad slots of this bin.
    if (tid < TMAX) {
        int c = s_offP[tid];
        #pragma unroll
        for (int w = 0; w < NWARPS; w++) {
            int tmp = s_whist[w * TMAX + tid];
            s_whist[w * TMAX + tid] = c;
            c += tmp;
        }
        // c now == s_offP[tid] + s_hist[tid]; zero up to next x8 boundary.
        int e = s_offP[tid + 1];
        for (int i = c; i < e; i++) s_sorted[i] = 0;
    }
    __syncthreads();

    // ---------- Phase 0c: direct scatter (2 LDS + 1 STS per token) ----------
    #pragma unroll
    for (int it = 0; it < LL / NTHREADS; ++it) {
        int t = it * NTHREADS + tid;
        int m = s_meta[t];
        int bin = (m >> 13) & 63;
        int idx = ((unsigned)m) >> 19;
        s_sorted[s_whist[wrow + bin] + idx] = m & 8191;
    }
    __syncthreads();

    // ---------- Phase 1: warp-per-bin FFMA gather, 8-deep LDG pipeline ------
    const float4* __restrict__ tab = reinterpret_cast<const float4*>(embX);
    #pragma unroll 1
    for (int slot = 0; slot < 3; ++slot) {
        const int bin = s_assign[warp * 3 + slot];
        const int beg = s_offP[bin];
        const int end = s_offP[bin + 1];        // (end-beg) % 8 == 0
        const int cnt = s_hist[bin];

        float ax = 0.f, ay = 0.f, az = 0.f, aw = 0.f;

        #pragma unroll 1
        for (int i = beg; i < end; i += 8) {
            int4 ia = *reinterpret_cast<const int4*>(s_sorted + i);
            int4 ib = *reinterpret_cast<const int4*>(s_sorted + i + 4);
            float4 e0 = tab[ia.x * 32 + lane];  // 8 independent LDG.128
            float4 e1 = tab[ia.y * 32 + lane];
            float4 e2 = tab[ia.z * 32 + lane];
            float4 e3 = tab[ia.w * 32 + lane];
            float4 e4 = tab[ib.x * 32 + lane];
            float4 e5 = tab[ib.y * 32 + lane];
            float4 e6 = tab[ib.z * 32 + lane];
            float4 e7 = tab[ib.w * 32 + lane];
            float w0 = s_wtab[ia.x];            // broadcast LDS
            float w1 = s_wtab[ia.y];
            float w2 = s_wtab[ia.z];
            float w3 = s_wtab[ia.w];
            float w4 = s_wtab[ib.x];
            float w5 = s_wtab[ib.y];
            float w6 = s_wtab[ib.z];
            float w7 = s_wtab[ib.w];
            ax = fmaf(w0, e0.x, ax); ay = fmaf(w0, e0.y, ay);
            az = fmaf(w0, e0.z, az); aw = fmaf(w0, e0.w, aw);
            ax = fmaf(w1, e1.x, ax); ay = fmaf(w1, e1.y, ay);
            az = fmaf(w1, e1.z, az); aw = fmaf(w1, e1.w, aw);
            ax = fmaf(w2, e2.x, ax); ay = fmaf(w2, e2.y, ay);
            az = fmaf(w2, e2.z, az); aw = fmaf(w2, e2.w, aw);
            ax = fmaf(w3, e3.x, ax); ay = fmaf(w3, e3.y, ay);
            az = fmaf(w3, e3.z, az); aw = fmaf(w3, e3.w, aw);
            ax = fmaf(w4, e4.x, ax); ay = fmaf(w4, e4.y, ay);
            az = fmaf(w4, e4.z, az); aw = fmaf(w4, e4.w, aw);
            ax = fmaf(w5, e5.x, ax); ay = fmaf(w5, e5.y, ay);
            az = fmaf(w5, e5.z, az); aw = fmaf(w5, e5.w, aw);
            ax = fmaf(w6, e6.x, ax); ay = fmaf(w6, e6.y, ay);
            az = fmaf(w6, e6.z, az); aw = fmaf(w6, e6.w, aw);
            ax = fmaf(w7, e7.x, ax); ay = fmaf(w7, e7.y, ay);
            az = fmaf(w7, e7.z, az); aw = fmaf(w7, e7.w, aw);
        }

        const float inv = 1.0f / ((float)cnt + 1e-6f);
        float4 o = make_float4(ax * inv, ay * inv, az * inv, aw * inv);
        reinterpret_cast<float4*>(out + ((size_t)b * TMAX + bin) * DD)[lane] = o;
    }
}

extern "C" void kernel_launch(void* const* d_in, const int* in_sizes, int n_in,
                              void* d_out, int out_size) {
    const float* X    = (const float*)d_in[0];   // [B, L, 2] fp32
    const float* embX = (const float*)d_in[1];   // [V, D] fp32
    const float* embW = (const float*)d_in[2];   // [V+1, 1] fp32
    float* out = (float*)d_out;                  // [B, TMAX, D] fp32

    embedder_kernel<<<BB, NTHREADS>>>(X, embX, embW, out);
}

// round 17
// speedup vs baseline: 1.5377x; 1.5377x over previous
#include <cuda_runtime.h>

// Problem constants
#define BB   256
#define LL   2048
#define DD   128
#define VV   6000
#define TMAX 48

#define NTHREADS 768
#define NWARPS   24
#define SORT_CAP (LL + 192)        // bins padded to x4 (max 3 pad each)

// Single monolithic kernel: one CTA per batch row. Identical structure to the
// 25.1us champion; only the thread count changed (512 -> 768) to raise
// occupancy 32 -> 48 warps/SM.
//   init   : per-CTA smem wtab[v] = exp(embW[v])  (24KB)
//   Phase 0: atomic-free counting sort; per-token sorted index computed during
//            the histogram pass (leader RMW + shfl); scatter = 2 LDS + 1 STS.
//   Phase 1: rank-balanced warp-per-bin (2 bins/warp) FFMA gather, unroll 4.
__global__ void __launch_bounds__(NTHREADS, 2)
embedder_kernel(const float* __restrict__ X,
                const float* __restrict__ embX,
                const float* __restrict__ embW,
                float* __restrict__ out) {
    const int b    = blockIdx.x;
    const int tid  = threadIdx.x;
    const int warp = tid >> 5;
    const int lane = tid & 31;
    const int wrow = warp * TMAX;

    __shared__ float s_wtab[VV + 4];                    // exp(embW[v]), 24KB
    __shared__ __align__(16) int s_sorted[SORT_CAP];    // bin-sorted ids (pad=0)
    __shared__ int s_meta[LL];          // id:13 | bin:6 | idx-in-(warp,bin):7
    __shared__ int s_whist[NWARPS * TMAX];  // counts, then in-place cursors
    __shared__ int s_hist[TMAX];
    __shared__ int s_offP[TMAX + 1];
    __shared__ int s_assign[TMAX];          // (warp,slot) -> bin

    // ---------- init: wtab + zeroing ----------
    #pragma unroll 1
    for (int i = tid; i < VV + 1; i += NTHREADS)
        s_wtab[i] = __expf(embW[i]);
    #pragma unroll 1
    for (int i = tid; i < SORT_CAP; i += NTHREADS) s_sorted[i] = 0;
    #pragma unroll 1
    for (int i = tid; i < NWARPS * TMAX; i += NTHREADS) s_whist[i] = 0;
    __syncthreads();

    // ---------- Phase 0a: meta + histogram + per-token sorted index ----------
    // Strided loop; tail boundary (2048 = 2*768 + 512) is warp-aligned, so the
    // loop-continue branch is warp-uniform and __match_any_sync is safe.
    const float2* __restrict__ Xb =
        reinterpret_cast<const float2*>(X) + (size_t)b * LL;
    #pragma unroll 1
    for (int t = tid; t < LL; t += NTHREADS) {
        float2 m = Xb[t];                    // m.x = T (>=0), m.y = id
        int bin = (int)m.x;                  // trunc == floor for T >= 0
        bin = min(max(bin, 0), TMAX - 1);
        int id = (int)m.y;                   // 1..5999 exact in fp32
        unsigned g = __match_any_sync(0xffffffffu, bin);
        int leader = __ffs(g) - 1;
        int rank = __popc(g & ((1u << lane) - 1u));
        int old = 0;
        if (lane == leader) {                // leader: plain RMW, race-free
            old = s_whist[wrow + bin];
            s_whist[wrow + bin] = old + __popc(g);
        }
        old = __shfl_sync(0xffffffffu, old, leader);
        // idx within (warp,bin) <= 3*32 = 96 -> fits 7 bits
        s_meta[t] = id | (bin << 13) | ((old + rank) << 19);
    }
    __syncthreads();

    // ---------- Phase 0b: totals ----------
    if (tid < TMAX) {
        int c = 0;
        #pragma unroll
        for (int w = 0; w < NWARPS; w++) c += s_whist[w * TMAX + tid];
        s_hist[tid] = c;
    }
    __syncthreads();

    // Rank bins by count + snake-partition into 24 warps x 2 slots.
    if (tid < TMAX) {
        int c = s_hist[tid];
        int r = 0;
        #pragma unroll 8
        for (int j = 0; j < TMAX; j++) {
            int cj = s_hist[j];
            r += (cj > c) || (cj == c && j < tid);
        }
        int w, slot;
        if (r < NWARPS) { w = r;                  slot = 0; }
        else            { w = 2 * NWARPS - 1 - r; slot = 1; }
        s_assign[w * 2 + slot] = tid;
    }
    // Padded (x4) exclusive prefix (pad ids = 0 == zero embX row).
    if (tid == 0) {
        int acc = 0;
        #pragma unroll
        for (int i = 0; i < TMAX; i++) {
            s_offP[i] = acc;
            acc += (s_hist[i] + 3) & ~3;
        }
        s_offP[TMAX] = acc;
    }
    __syncthreads();

    // In-place transform: s_whist[w][bin] := cursor base for (warp w, bin).
    if (tid < TMAX) {
        int c = s_offP[tid];
        #pragma unroll
        for (int w = 0; w < NWARPS; w++) {
            int tmp = s_whist[w * TMAX + tid];
            s_whist[w * TMAX + tid] = c;
            c += tmp;
        }
    }
    __syncthreads();

    // ---------- Phase 0c: direct scatter (2 LDS + 1 STS per token) ----------
    #pragma unroll 1
    for (int t = tid; t < LL; t += NTHREADS) {
        int m = s_meta[t];
        int bin = (m >> 13) & 63;
        int idx = ((unsigned)m) >> 19;
        s_sorted[s_whist[wrow + bin] + idx] = m & 8191;
    }
    __syncthreads();

    // ---------- Phase 1: warp-per-bin FFMA gather, unroll 4 ----------
    const float4* __restrict__ tab = reinterpret_cast<const float4*>(embX);
    #pragma unroll 1
    for (int slot = 0; slot < 2; ++slot) {
        const int bin = s_assign[warp * 2 + slot];
        const int beg = s_offP[bin];
        const int end = s_offP[bin + 1];        // (end-beg) % 4 == 0
        const int cnt = s_hist[bin];

        float ax = 0.f, ay = 0.f, az = 0.f, aw = 0.f;

        #pragma unroll 1
        for (int i = beg; i < end; i += 4) {
            int4 ids = *reinterpret_cast<const int4*>(s_sorted + i);
            float w0 = s_wtab[ids.x];           // broadcast LDS
            float w1 = s_wtab[ids.y];
            float w2 = s_wtab[ids.z];
            float w3 = s_wtab[ids.w];
            float4 e0 = tab[ids.x * 32 + lane]; // 4 in-flight LDG.128
            float4 e1 = tab[ids.y * 32 + lane];
            float4 e2 = tab[ids.z * 32 + lane];
            float4 e3 = tab[ids.w * 32 + lane];
            ax = fmaf(w0, e0.x, ax); ay = fmaf(w0, e0.y, ay);
            az = fmaf(w0, e0.z, az); aw = fmaf(w0, e0.w, aw);
            ax = fmaf(w1, e1.x, ax); ay = fmaf(w1, e1.y, ay);
            az = fmaf(w1, e1.z, az); aw = fmaf(w1, e1.w, aw);
            ax = fmaf(w2, e2.x, ax); ay = fmaf(w2, e2.y, ay);
            az = fmaf(w2, e2.z, az); aw = fmaf(w2, e2.w, aw);
            ax = fmaf(w3, e3.x, ax); ay = fmaf(w3, e3.y, ay);
            az = fmaf(w3, e3.z, az); aw = fmaf(w3, e3.w, aw);
        }

        const float inv = 1.0f / ((float)cnt + 1e-6f);
        float4 o = make_float4(ax * inv, ay * inv, az * inv, aw * inv);
        reinterpret_cast<float4*>(out + ((size_t)b * TMAX + bin) * DD)[lane] = o;
    }
}

extern "C" void kernel_launch(void* const* d_in, const int* in_sizes, int n_in,
                              void* d_out, int out_size) {
    const float* X    = (const float*)d_in[0];   // [B, L, 2] fp32
    const float* embX = (const float*)d_in[1];   // [V, D] fp32
    const float* embW = (const float*)d_in[2];   // [V+1, 1] fp32
    float* out = (float*)d_out;                  // [B, TMAX, D] fp32

    embedder_kernel<<<BB, NTHREADS>>>(X, embX, embW, out);
}